// round 10
// baseline (speedup 1.0000x reference)
#include <cuda_runtime.h>
#include <cuda_bf16.h>
#include <cstdint>

// ============================================================================
// TransformerEncoderLayer (B=4,S=4096,D=1024, 8 local heads) on sm_103 base.
// GEMMs: mma.sync.m16n8k16 bf16, 3-product double-bf16 split, fp32 accum.
// R9: BK=32 (64B rows, SW64 swizzle), 3 stages x 32KB = 96KB smem ->
// 2 CTAs/SM (4 warps/SMSP) with __launch_bounds__(256,2); staggered fragment
// loads to keep peak live regs < 128. Attn: 2-thread dots + shfl.
// ============================================================================

static const int M_TOK = 16384;
static const int DM    = 1024;

// ---------------- scratch (__device__ globals; allocation-free rule) --------
__device__ float g_qkv[16384 * 3072];              // packed q|k|v per token
__device__ float g_bqkv[3072];                     // concat bias
__device__ __nv_bfloat16 g_xhi [16384 * 1024];
__device__ __nv_bfloat16 g_xlo [16384 * 1024];
__device__ __nv_bfloat16 g_aohi[16384 * 1024];
__device__ __nv_bfloat16 g_aolo[16384 * 1024];
__device__ __nv_bfloat16 g_hhi [16384 * 1024];
__device__ __nv_bfloat16 g_hlo [16384 * 1024];
__device__ __nv_bfloat16 g_wthi[5][1024 * 1024];   // W^T hi [n][k] (q,k,v contiguous)
__device__ __nv_bfloat16 g_wtlo[5][1024 * 1024];   // W^T lo [n][k]

// ---------------- PTX helpers (sm_80-level; valid on sm_103 base) -----------
__device__ __forceinline__ uint32_t smem_u32(const void* p) {
    uint32_t a;
    asm("{ .reg .u64 t; cvta.to.shared.u64 t, %1; cvt.u32.u64 %0, t; }"
        : "=r"(a) : "l"(p));
    return a;
}
__device__ __forceinline__ void cpasync16(uint32_t saddr, const void* g) {
    asm volatile("cp.async.cg.shared.global [%0], [%1], 16;"
                 :: "r"(saddr), "l"(g));
}
#define CP_COMMIT() asm volatile("cp.async.commit_group;" ::: "memory")
#define CP_WAIT1()  asm volatile("cp.async.wait_group 1;" ::: "memory")

__device__ __forceinline__ void ldsm4(uint32_t r[4], uint32_t addr) {
    asm volatile("ldmatrix.sync.aligned.m8n8.x4.shared.b16 {%0,%1,%2,%3}, [%4];"
                 : "=r"(r[0]), "=r"(r[1]), "=r"(r[2]), "=r"(r[3]) : "r"(addr));
}
__device__ __forceinline__ void mma16816(float c[4], const uint32_t a[4],
                                         uint32_t b0, uint32_t b1) {
    asm volatile(
        "mma.sync.aligned.m16n8k16.row.col.f32.bf16.bf16.f32 "
        "{%0,%1,%2,%3}, {%4,%5,%6,%7}, {%8,%9}, {%0,%1,%2,%3};"
        : "+f"(c[0]), "+f"(c[1]), "+f"(c[2]), "+f"(c[3])
        : "r"(a[0]), "r"(a[1]), "r"(a[2]), "r"(a[3]), "r"(b0), "r"(b1));
}
__device__ __forceinline__ uint32_t pack_hi_lo(float x, float y, uint32_t& lo_out) {
    const __nv_bfloat16 hx = __float2bfloat16(x);
    const __nv_bfloat16 hy = __float2bfloat16(y);
    const __nv_bfloat16 lx = __float2bfloat16(x - __bfloat162float(hx));
    const __nv_bfloat16 ly = __float2bfloat16(y - __bfloat162float(hy));
    union { __nv_bfloat16 b[2]; uint32_t u; } h, l;
    h.b[0] = hx; h.b[1] = hy; l.b[0] = lx; l.b[1] = ly;
    lo_out = l.u;
    return h.u;
}

// smem: 3 stages x 32KB; stage = Ahi@0(8K), Alo@8K, Bhi@16K, Blo@24K.
// Each operand: 128 rows x 64B (BK=32 bf16). SW64-style swizzle:
//   phys = row*64 + (colbytes ^ (((row>>1)&3)<<4))  (conflict-free for
//   both cp.async 16B stores and ldmatrix 16B row reads).
static const int STAGE_BYTES = 32768;
static const int SMEM_DYN    = 3 * STAGE_BYTES;    // 96KB -> 2 CTAs/SM

// ============================================================================
// GEMM D[M x N] = A @ W + bias. A split (hi,lo) [m][1024], W^T split [n][1024].
// CTA 128x128, 256 thr (8 warps: 2m x 4n, warp tile 64x32), BK=32, 3 stages.
// Out: fp32 Cf and/or bf16 split (Chi,Clo) with leading dim Nld; optional ReLU.
// ============================================================================
__global__ __launch_bounds__(256, 2)
void gemm_mma_bf16x3(const __nv_bfloat16* __restrict__ Ahi, const __nv_bfloat16* __restrict__ Alo,
                     const __nv_bfloat16* __restrict__ Bhi, const __nv_bfloat16* __restrict__ Blo,
                     const float* __restrict__ bias,
                     float* __restrict__ Cf,
                     __nv_bfloat16* __restrict__ Chi, __nv_bfloat16* __restrict__ Clo,
                     int relu, int Nld)
{
    extern __shared__ char smem[];
    const uint32_t sbase = smem_u32(smem);
    const int tid  = threadIdx.x;
    const int lane = tid & 31;
    const int wid  = tid >> 5;
    const int wm   = wid >> 2;          // 0..1  (m: 64 each)
    const int wn   = wid & 3;           // 0..3  (n: 32 each)
    const int m0   = blockIdx.y * 128;
    const int n0   = blockIdx.x * 128;

    float acc[4][4][4];
    #pragma unroll
    for (int a = 0; a < 4; ++a)
        #pragma unroll
        for (int n = 0; n < 4; ++n)
            #pragma unroll
            for (int e = 0; e < 4; ++e) acc[a][n][e] = 0.0f;

    // ---- gmem->smem: 4 granules (16B) per 64B row; 2 rows/thread/operand ---
    const int lrow = tid >> 2;                  // 0..63, + j*64
    const int lc   = tid & 3;                   // 16B granule within 64B row
    auto issue_tile = [&](int t) {
        const uint32_t st = sbase + (uint32_t)(t % 3) * (uint32_t)STAGE_BYTES;
        const int kt = t * 32;
        #pragma unroll
        for (int j = 0; j < 2; ++j) {
            const int row = j * 64 + lrow;
            const uint32_t so = (uint32_t)row * 64u +
                                (((uint32_t)lc * 16u) ^ ((((uint32_t)row >> 1) & 3u) << 4));
            const size_t ga = (size_t)(m0 + row) * 1024 + kt + lc * 8;
            const size_t gb = (size_t)(n0 + row) * 1024 + kt + lc * 8;
            cpasync16(st +          so, Ahi + ga);
            cpasync16(st +  8192u + so, Alo + ga);
            cpasync16(st + 16384u + so, Bhi + gb);
            cpasync16(st + 24576u + so, Blo + gb);
        }
    };

    // ---- ldmatrix per-thread constants -------------------------------------
    const int mi = lane >> 3, li = lane & 7;
    const int      arow0 = wm * 64 + ((mi & 1) << 3) + li;      // + a*16
    const uint32_t acb0  = ((uint32_t)(mi >> 1)) << 4;          // 16B half of k16 chunk
    const int      brow0 = wn * 32 + ((mi >> 1) << 3) + li;     // + g*16
    const uint32_t bcb0  = ((uint32_t)(mi & 1)) << 4;

    auto addrOp = [&](uint32_t opbase, int row, uint32_t colb) {
        return opbase + (uint32_t)row * 64u +
               (colb ^ ((((uint32_t)row >> 1) & 3u) << 4));
    };

    // ---- pipeline: 3-stage cp.async, issue-before-compute ------------------
    issue_tile(0); CP_COMMIT();
    issue_tile(1); CP_COMMIT();

    for (int t = 0; t < 32; ++t) {
        CP_WAIT1();
        __syncthreads();
        if (t + 2 < 32) issue_tile(t + 2);
        CP_COMMIT();

        const uint32_t st = sbase + (uint32_t)(t % 3) * (uint32_t)STAGE_BYTES;
        #pragma unroll
        for (int ks = 0; ks < 2; ++ks) {
            const uint32_t kc = (uint32_t)ks * 32u;   // bytes within 64B row
            uint32_t aH[4][4], aL[4][4], bH[2][4], bL[2][4];

            // Staggered (R6) ordering keeps peak live registers < 128.
            #pragma unroll
            for (int a = 0; a < 4; ++a)
                ldsm4(aH[a], addrOp(st,          arow0 + a * 16, kc + acb0));
            #pragma unroll
            for (int g = 0; g < 2; ++g)
                ldsm4(bH[g], addrOp(st + 16384u, brow0 + g * 16, kc + bcb0));
            #pragma unroll
            for (int a = 0; a < 4; ++a)
                #pragma unroll
                for (int n = 0; n < 4; ++n)
                    mma16816(acc[a][n], aH[a], bH[n >> 1][(n & 1) * 2], bH[n >> 1][(n & 1) * 2 + 1]);

            #pragma unroll
            for (int g = 0; g < 2; ++g)
                ldsm4(bL[g], addrOp(st + 24576u, brow0 + g * 16, kc + bcb0));
            #pragma unroll
            for (int a = 0; a < 4; ++a)
                #pragma unroll
                for (int n = 0; n < 4; ++n)
                    mma16816(acc[a][n], aH[a], bL[n >> 1][(n & 1) * 2], bL[n >> 1][(n & 1) * 2 + 1]);

            #pragma unroll
            for (int a = 0; a < 4; ++a)
                ldsm4(aL[a], addrOp(st +  8192u, arow0 + a * 16, kc + acb0));
            #pragma unroll
            for (int a = 0; a < 4; ++a)
                #pragma unroll
                for (int n = 0; n < 4; ++n)
                    mma16816(acc[a][n], aL[a], bH[n >> 1][(n & 1) * 2], bH[n >> 1][(n & 1) * 2 + 1]);
        }
    }

    // ---- epilogue ----------------------------------------------------------
    const int er0 = m0 + wm * 64 + (lane >> 2);
    const int ec0 = n0 + wn * 32 + (lane & 3) * 2;
    #pragma unroll
    for (int a = 0; a < 4; ++a) {
        #pragma unroll
        for (int n = 0; n < 4; ++n) {
            const int r0 = er0 + a * 16, r1 = r0 + 8;
            const int c  = ec0 + n * 8;
            const float b0 = __ldg(bias + c), b1 = __ldg(bias + c + 1);
            float v00 = acc[a][n][0] + b0, v01 = acc[a][n][1] + b1;
            float v10 = acc[a][n][2] + b0, v11 = acc[a][n][3] + b1;
            if (relu) {
                v00 = fmaxf(v00, 0.0f); v01 = fmaxf(v01, 0.0f);
                v10 = fmaxf(v10, 0.0f); v11 = fmaxf(v11, 0.0f);
            }
            if (Cf) {
                *(float2*)(Cf + (size_t)r0 * Nld + c) = make_float2(v00, v01);
                *(float2*)(Cf + (size_t)r1 * Nld + c) = make_float2(v10, v11);
            }
            if (Chi) {
                uint32_t l0, l1;
                const uint32_t h0 = pack_hi_lo(v00, v01, l0);
                const uint32_t h1 = pack_hi_lo(v10, v11, l1);
                *(uint32_t*)(Chi + (size_t)r0 * Nld + c) = h0;
                *(uint32_t*)(Clo + (size_t)r0 * Nld + c) = l0;
                *(uint32_t*)(Chi + (size_t)r1 * Nld + c) = h1;
                *(uint32_t*)(Clo + (size_t)r1 * Nld + c) = l1;
            }
        }
    }
}

// ============================================================================
// fp32 -> bf16 hi/lo elementwise split (for x)
// ============================================================================
__global__ void split_kernel(const float* __restrict__ X,
                             __nv_bfloat16* __restrict__ H,
                             __nv_bfloat16* __restrict__ L, int n4)
{
    const int i = blockIdx.x * blockDim.x + threadIdx.x;
    if (i >= n4) return;
    const float4 v = ((const float4*)X)[i];
    const float vv[4] = {v.x, v.y, v.z, v.w};
    union { __nv_bfloat16 b[4]; uint2 u; } hh, ll;
    #pragma unroll
    for (int e = 0; e < 4; ++e) {
        const __nv_bfloat16 hb = __float2bfloat16(vv[e]);
        hh.b[e] = hb;
        ll.b[e] = __float2bfloat16(vv[e] - __bfloat162float(hb));
    }
    ((uint2*)H)[i] = hh.u;
    ((uint2*)L)[i] = ll.u;
}

// ============================================================================
// All 5 weights: W [k][n] fp32 -> W^T hi/lo [n][k] bf16. gridDim.z selects W.
// ============================================================================
__global__ void wconvert_kernel(const float* __restrict__ W0, const float* __restrict__ W1,
                                const float* __restrict__ W2, const float* __restrict__ W3,
                                const float* __restrict__ W4,
                                __nv_bfloat16* __restrict__ Thi,
                                __nv_bfloat16* __restrict__ Tlo)
{
    __shared__ float t[32][33];
    const int wi = blockIdx.z;
    const float* W = (wi == 0) ? W0 : (wi == 1) ? W1 : (wi == 2) ? W2
                   : (wi == 3) ? W3 : W4;
    __nv_bfloat16* H = Thi + (size_t)wi * 1024 * 1024;
    __nv_bfloat16* L = Tlo + (size_t)wi * 1024 * 1024;

    const int k0 = blockIdx.y * 32, n0 = blockIdx.x * 32;
    const int tx = threadIdx.x, ty = threadIdx.y;  // 32 x 8
    #pragma unroll
    for (int i = 0; i < 4; ++i)
        t[ty + i*8][tx] = W[(size_t)(k0 + ty + i*8) * 1024 + n0 + tx];
    __syncthreads();
    #pragma unroll
    for (int i = 0; i < 4; ++i) {
        const float v = t[tx][ty + i*8];
        const size_t o = (size_t)(n0 + ty + i*8) * 1024 + k0 + tx;
        const __nv_bfloat16 hb = __float2bfloat16(v);
        H[o] = hb;
        L[o] = __float2bfloat16(v - __bfloat162float(hb));
    }
}

// ============================================================================
// Per-token 8-head local attention; packed qkv [tok][3072] input;
// 2 tokens per 256-thread block; 2-thread dots + shfl reduce.
// ============================================================================
__global__ __launch_bounds__(256)
void attn_kernel(const float* __restrict__ QKV,
                 __nv_bfloat16* __restrict__ Ohi, __nv_bfloat16* __restrict__ Olo,
                 float* __restrict__ AW)
{
    __shared__ float sq[2][8 * 132];
    __shared__ float sk[2][8 * 132];
    __shared__ float sv[2][8 * 132];
    __shared__ float sw[2][64];

    const int sub = threadIdx.x >> 7;            // token within block
    const int tid = threadIdx.x & 127;
    const size_t tok  = (size_t)blockIdx.x * 2 + sub;
    const size_t base = tok * 3072;

    float* q_ = sq[sub]; float* k_ = sk[sub]; float* v_ = sv[sub]; float* w_ = sw[sub];

    for (int i = tid; i < 1024; i += 128) {
        const int h = i >> 7, d = i & 127;
        q_[h * 132 + d] = QKV[base + i];
        k_[h * 132 + d] = QKV[base + 1024 + i];
        v_[h * 132 + d] = QKV[base + 2048 + i];
    }
    __syncthreads();

    // scores: 2 threads per (h,t) dot, 64 elements each, shfl-combine
    {
        const int s    = tid >> 1;               // 0..63
        const int half = tid & 1;
        const int h = s >> 3, t = s & 7;
        const int d0 = half * 64;
        float sum = 0.0f;
        #pragma unroll 8
        for (int d = 0; d < 64; d++)
            sum += q_[h * 132 + d0 + d] * k_[t * 132 + d0 + d];
        sum += __shfl_xor_sync(0xFFFFFFFFu, sum, 1);
        if (!half) w_[s] = sum * 0.08838834764831845f;   // 1/sqrt(128)
    }
    __syncthreads();

    if (tid < 8) {
        const int h = tid;
        float m = w_[h * 8];
        #pragma unroll
        for (int t = 1; t < 8; t++) m = fmaxf(m, w_[h * 8 + t]);
        float e[8], sum = 0.0f;
        #pragma unroll
        for (int t = 0; t < 8; t++) { e[t] = expf(w_[h * 8 + t] - m); sum += e[t]; }
        const float inv = 1.0f / sum;
        #pragma unroll
        for (int t = 0; t < 8; t++) w_[h * 8 + t] = e[t] * inv;
    }
    __syncthreads();

    const int d = tid;
    const size_t obase = tok * 1024;
    #pragma unroll
    for (int h = 0; h < 8; h++) {
        float o = 0.0f;
        #pragma unroll
        for (int t = 0; t < 8; t++)
            o += w_[h * 8 + t] * v_[t * 132 + d];
        const __nv_bfloat16 hb = __float2bfloat16(o);
        Ohi[obase + h * 128 + d] = hb;
        Olo[obase + h * 128 + d] = __float2bfloat16(o - __bfloat162float(hb));
    }

    if (AW != nullptr && tid < 64)
        AW[tok * 64 + tid] = w_[tid];
}

// ============================================================================
extern "C" void kernel_launch(void* const* d_in, const int* in_sizes, int n_in,
                              void* d_out, int out_size)
{
    (void)in_sizes; (void)n_in;
    const float* x  = (const float*)d_in[0];
    const float* bq = (const float*)d_in[2];
    const float* bk = (const float*)d_in[4];
    const float* bv = (const float*)d_in[6];
    const float* b1 = (const float*)d_in[8];
    const float* b2 = (const float*)d_in[10];
    float* out = (float*)d_out;

    float *qkv, *bqkv;
    __nv_bfloat16 *xhi, *xlo, *aohi, *aolo, *hhi, *hlo, *wthi, *wtlo;
    cudaGetSymbolAddress((void**)&qkv,  g_qkv);
    cudaGetSymbolAddress((void**)&bqkv, g_bqkv);
    cudaGetSymbolAddress((void**)&xhi,  g_xhi);
    cudaGetSymbolAddress((void**)&xlo,  g_xlo);
    cudaGetSymbolAddress((void**)&aohi, g_aohi);
    cudaGetSymbolAddress((void**)&aolo, g_aolo);
    cudaGetSymbolAddress((void**)&hhi,  g_hhi);
    cudaGetSymbolAddress((void**)&hlo,  g_hlo);
    cudaGetSymbolAddress((void**)&wthi, g_wthi);
    cudaGetSymbolAddress((void**)&wtlo, g_wtlo);

    cudaFuncSetAttribute(gemm_mma_bf16x3,
                         cudaFuncAttributeMaxDynamicSharedMemorySize, SMEM_DYN);

    const int ff_elems   = M_TOK * DM;
    const int attn_elems = M_TOK * 64;
    float* aw = (out_size >= ff_elems + attn_elems) ? (out + ff_elems) : nullptr;

    // ---- prep: split x; all-5 weight transpose+split; concat qkv bias -----
    split_kernel<<<(M_TOK * DM / 4 + 255) / 256, 256>>>(x, xhi, xlo, M_TOK * DM / 4);
    wconvert_kernel<<<dim3(32, 32, 5), dim3(32, 8)>>>(
        (const float*)d_in[1], (const float*)d_in[3], (const float*)d_in[5],
        (const float*)d_in[7], (const float*)d_in[9], wthi, wtlo);
    cudaMemcpyAsync(bqkv,        bq, 1024 * sizeof(float), cudaMemcpyDeviceToDevice);
    cudaMemcpyAsync(bqkv + 1024, bk, 1024 * sizeof(float), cudaMemcpyDeviceToDevice);
    cudaMemcpyAsync(bqkv + 2048, bv, 1024 * sizeof(float), cudaMemcpyDeviceToDevice);

    dim3 block(256);

    // ---- fused QKV projection: N=3072, packed [tok][3072] fp32 ------------
    gemm_mma_bf16x3<<<dim3(24, 128), block, SMEM_DYN>>>(xhi, xlo,
        wthi, wtlo, bqkv, qkv, nullptr, nullptr, 0, 3072);

    // ---- attention (emits bf16 split for FFN1) ----------------------------
    attn_kernel<<<M_TOK / 2, 256>>>(qkv, aohi, aolo, aw);

    // ---- FFN --------------------------------------------------------------
    gemm_mma_bf16x3<<<dim3(8, 128), block, SMEM_DYN>>>(aohi, aolo,
        wthi + 3 * (size_t)DM * DM, wtlo + 3 * (size_t)DM * DM, b1,
        nullptr, hhi, hlo, 1, 1024);
    gemm_mma_bf16x3<<<dim3(8, 128), block, SMEM_DYN>>>(hhi, hlo,
        wthi + 4 * (size_t)DM * DM, wtlo + 4 * (size_t)DM * DM, b2,
        out, nullptr, nullptr, 0, 1024);
}

// round 14
// speedup vs baseline: 1.3737x; 1.3737x over previous
#include <cuda_runtime.h>
#include <cuda_fp16.h>
#include <cstdint>

// ============================================================================
// TransformerEncoderLayer (B=4,S=4096,D=1024, 8 local heads) on sm_103 base.
// R10: fp16x2 GEMMs — activations single fp16, weights split fp16 hi/lo,
// 2 MMA products (A*Whi + A*Wlo), fp32 accum. 33% fewer HMMA than bf16x3.
// Skeleton: proven R6/R8 core (128x128 CTA, 256 thr, BK=64, SW128, 3-stage
// cp.async, issue-before-compute) + fused QKV (N=3072) + R8 attn.
// ============================================================================

static const int M_TOK = 16384;
static const int DM    = 1024;

// ---------------- scratch (__device__ globals; allocation-free rule) --------
__device__ float g_qkv[16384 * 3072];              // packed q|k|v per token
__device__ float g_bqkv[3072];                     // concat bias
__device__ __half g_xh [16384 * 1024];             // x  as fp16
__device__ __half g_aoh[16384 * 1024];             // attn out as fp16
__device__ __half g_hh [16384 * 1024];             // ffn1 out as fp16
__device__ __half g_wthi[5][1024 * 1024];          // W^T hi [n][k] (q,k,v contiguous)
__device__ __half g_wtlo[5][1024 * 1024];          // W^T lo [n][k]

// ---------------- PTX helpers (sm_80-level; valid on sm_103 base) -----------
__device__ __forceinline__ uint32_t smem_u32(const void* p) {
    uint32_t a;
    asm("{ .reg .u64 t; cvta.to.shared.u64 t, %1; cvt.u32.u64 %0, t; }"
        : "=r"(a) : "l"(p));
    return a;
}
__device__ __forceinline__ void cpasync16(uint32_t saddr, const void* g) {
    asm volatile("cp.async.cg.shared.global [%0], [%1], 16;"
                 :: "r"(saddr), "l"(g));
}
#define CP_COMMIT() asm volatile("cp.async.commit_group;" ::: "memory")
#define CP_WAIT1()  asm volatile("cp.async.wait_group 1;" ::: "memory")

__device__ __forceinline__ void ldsm4(uint32_t r[4], uint32_t addr) {
    asm volatile("ldmatrix.sync.aligned.m8n8.x4.shared.b16 {%0,%1,%2,%3}, [%4];"
                 : "=r"(r[0]), "=r"(r[1]), "=r"(r[2]), "=r"(r[3]) : "r"(addr));
}
__device__ __forceinline__ void mma16816h(float c[4], const uint32_t a[4],
                                          uint32_t b0, uint32_t b1) {
    asm volatile(
        "mma.sync.aligned.m16n8k16.row.col.f32.f16.f16.f32 "
        "{%0,%1,%2,%3}, {%4,%5,%6,%7}, {%8,%9}, {%0,%1,%2,%3};"
        : "+f"(c[0]), "+f"(c[1]), "+f"(c[2]), "+f"(c[3])
        : "r"(a[0]), "r"(a[1]), "r"(a[2]), "r"(a[3]), "r"(b0), "r"(b1));
}

// smem: 3 stages x 48KB; stage = A@0(16K), Whi@16K(16K), Wlo@32K(16K).
// Each operand: 128 rows x 128B (BK=64 fp16), SW128 swizzle.
static const int STAGE_BYTES = 49152;
static const int SMEM_DYN    = 3 * STAGE_BYTES;    // 144KB

// ============================================================================
// GEMM D[M x N] = A @ W + bias. A fp16 [m][1024], W^T split fp16 hi/lo [n][1024].
// CTA 128x128, 256 thr (8 warps: 2m x 4n, warp tile 64x32), BK=64, 3 stages.
// Out: fp32 Cf and/or fp16 Ch with leading dim Nld; optional ReLU.
// ============================================================================
__global__ __launch_bounds__(256, 1)
void gemm_mma_f16x2(const __half* __restrict__ A,
                    const __half* __restrict__ Bhi, const __half* __restrict__ Blo,
                    const float* __restrict__ bias,
                    float* __restrict__ Cf, __half* __restrict__ Ch,
                    int relu, int Nld)
{
    extern __shared__ char smem[];
    const uint32_t sbase = smem_u32(smem);
    const int tid  = threadIdx.x;
    const int lane = tid & 31;
    const int wid  = tid >> 5;
    const int wm   = wid >> 2;          // 0..1  (m: 64 each)
    const int wn   = wid & 3;           // 0..3  (n: 32 each)
    const int m0   = blockIdx.y * 128;
    const int n0   = blockIdx.x * 128;

    float acc[4][4][4];
    #pragma unroll
    for (int a = 0; a < 4; ++a)
        #pragma unroll
        for (int n = 0; n < 4; ++n)
            #pragma unroll
            for (int e = 0; e < 4; ++e) acc[a][n][e] = 0.0f;

    // ---- gmem->smem mapping: 8 threads per 128B row, all 8 granules -------
    const int lrow = tid >> 3;                  // 0..31, + j*32
    const int lc   = tid & 7;                   // 16B granule
    auto issue_tile = [&](int t) {
        const uint32_t st = sbase + (uint32_t)(t % 3) * (uint32_t)STAGE_BYTES;
        const int kt = t * 64;
        #pragma unroll
        for (int j = 0; j < 4; ++j) {
            const int row = j * 32 + lrow;
            const uint32_t so = (uint32_t)row * 128u +
                                (((uint32_t)lc * 16u) ^ (((uint32_t)row & 7u) << 4));
            const size_t ga = (size_t)(m0 + row) * 1024 + kt + lc * 8;
            const size_t gb = (size_t)(n0 + row) * 1024 + kt + lc * 8;
            cpasync16(st +          so, A   + ga);
            cpasync16(st + 16384u + so, Bhi + gb);
            cpasync16(st + 32768u + so, Blo + gb);
        }
    };

    // ---- ldmatrix per-thread constants -------------------------------------
    const int mi = lane >> 3, li = lane & 7;
    const uint32_t axor  = ((uint32_t)li) << 4;                 // swizzle xor
    const int      arow0 = wm * 64 + ((mi & 1) << 3) + li;      // + a*16
    const uint32_t acb0  = ((uint32_t)(mi >> 1)) << 4;          // + ks*32
    const int      brow0 = wn * 32 + ((mi >> 1) << 3) + li;     // + g*16
    const uint32_t bcb0  = ((uint32_t)(mi & 1)) << 4;           // + ks*32

    // ---- pipeline: 3-stage cp.async, issue-before-compute ------------------
    issue_tile(0); CP_COMMIT();
    issue_tile(1); CP_COMMIT();

    for (int t = 0; t < 16; ++t) {
        CP_WAIT1();
        __syncthreads();
        if (t + 2 < 16) issue_tile(t + 2);
        CP_COMMIT();

        const uint32_t st = sbase + (uint32_t)(t % 3) * (uint32_t)STAGE_BYTES;
        #pragma unroll
        for (int ks = 0; ks < 4; ++ks) {
            const uint32_t kc = (uint32_t)ks * 32u;
            uint32_t aF[4][4], bH[2][4], bL[2][4];

            #pragma unroll
            for (int a = 0; a < 4; ++a)
                ldsm4(aF[a], st + (uint32_t)(arow0 + a * 16) * 128u + ((kc + acb0) ^ axor));
            #pragma unroll
            for (int g = 0; g < 2; ++g)
                ldsm4(bH[g], st + 16384u + (uint32_t)(brow0 + g * 16) * 128u + ((kc + bcb0) ^ axor));
            #pragma unroll
            for (int a = 0; a < 4; ++a)
                #pragma unroll
                for (int n = 0; n < 4; ++n)
                    mma16816h(acc[a][n], aF[a], bH[n >> 1][(n & 1) * 2], bH[n >> 1][(n & 1) * 2 + 1]);

            #pragma unroll
            for (int g = 0; g < 2; ++g)
                ldsm4(bL[g], st + 32768u + (uint32_t)(brow0 + g * 16) * 128u + ((kc + bcb0) ^ axor));
            #pragma unroll
            for (int a = 0; a < 4; ++a)
                #pragma unroll
                for (int n = 0; n < 4; ++n)
                    mma16816h(acc[a][n], aF[a], bL[n >> 1][(n & 1) * 2], bL[n >> 1][(n & 1) * 2 + 1]);
        }
    }

    // ---- epilogue ----------------------------------------------------------
    const int er0 = m0 + wm * 64 + (lane >> 2);
    const int ec0 = n0 + wn * 32 + (lane & 3) * 2;
    #pragma unroll
    for (int a = 0; a < 4; ++a) {
        #pragma unroll
        for (int n = 0; n < 4; ++n) {
            const int r0 = er0 + a * 16, r1 = r0 + 8;
            const int c  = ec0 + n * 8;
            const float b0 = __ldg(bias + c), b1 = __ldg(bias + c + 1);
            float v00 = acc[a][n][0] + b0, v01 = acc[a][n][1] + b1;
            float v10 = acc[a][n][2] + b0, v11 = acc[a][n][3] + b1;
            if (relu) {
                v00 = fmaxf(v00, 0.0f); v01 = fmaxf(v01, 0.0f);
                v10 = fmaxf(v10, 0.0f); v11 = fmaxf(v11, 0.0f);
            }
            if (Cf) {
                *(float2*)(Cf + (size_t)r0 * Nld + c) = make_float2(v00, v01);
                *(float2*)(Cf + (size_t)r1 * Nld + c) = make_float2(v10, v11);
            }
            if (Ch) {
                const __half2 h0 = __floats2half2_rn(v00, v01);
                const __half2 h1 = __floats2half2_rn(v10, v11);
                *(__half2*)(Ch + (size_t)r0 * Nld + c) = h0;
                *(__half2*)(Ch + (size_t)r1 * Nld + c) = h1;
            }
        }
    }
}

// ============================================================================
// fp32 -> fp16 elementwise convert (for x)
// ============================================================================
__global__ void xconvert_kernel(const float* __restrict__ X,
                                __half* __restrict__ H, int n4)
{
    const int i = blockIdx.x * blockDim.x + threadIdx.x;
    if (i >= n4) return;
    const float4 v = ((const float4*)X)[i];
    __half2 h0 = __floats2half2_rn(v.x, v.y);
    __half2 h1 = __floats2half2_rn(v.z, v.w);
    ((__half2*)H)[i * 2 + 0] = h0;
    ((__half2*)H)[i * 2 + 1] = h1;
}

// ============================================================================
// All 5 weights: W [k][n] fp32 -> W^T hi/lo fp16 [n][k]. gridDim.z selects W.
// ============================================================================
__global__ void wconvert_kernel(const float* __restrict__ W0, const float* __restrict__ W1,
                                const float* __restrict__ W2, const float* __restrict__ W3,
                                const float* __restrict__ W4,
                                __half* __restrict__ Thi, __half* __restrict__ Tlo)
{
    __shared__ float t[32][33];
    const int wi = blockIdx.z;
    const float* W = (wi == 0) ? W0 : (wi == 1) ? W1 : (wi == 2) ? W2
                   : (wi == 3) ? W3 : W4;
    __half* H = Thi + (size_t)wi * 1024 * 1024;
    __half* L = Tlo + (size_t)wi * 1024 * 1024;

    const int k0 = blockIdx.y * 32, n0 = blockIdx.x * 32;
    const int tx = threadIdx.x, ty = threadIdx.y;  // 32 x 8
    #pragma unroll
    for (int i = 0; i < 4; ++i)
        t[ty + i*8][tx] = W[(size_t)(k0 + ty + i*8) * 1024 + n0 + tx];
    __syncthreads();
    #pragma unroll
    for (int i = 0; i < 4; ++i) {
        const float v = t[tx][ty + i*8];
        const size_t o = (size_t)(n0 + ty + i*8) * 1024 + k0 + tx;
        const __half hb = __float2half_rn(v);
        H[o] = hb;
        L[o] = __float2half_rn(v - __half2float(hb));
    }
}

// ============================================================================
// Per-token 8-head local attention; packed qkv [tok][3072] input;
// 2 tokens per 256-thread block; emits fp16 output + attn weights. (R8 form.)
// ============================================================================
__global__ __launch_bounds__(256)
void attn_kernel(const float* __restrict__ QKV,
                 __half* __restrict__ Oh, float* __restrict__ AW)
{
    __shared__ float sq[2][8 * 132];
    __shared__ float sk[2][8 * 132];
    __shared__ float sv[2][8 * 132];
    __shared__ float sw[2][64];

    const int sub = threadIdx.x >> 7;            // token within block
    const int tid = threadIdx.x & 127;
    const size_t tok  = (size_t)blockIdx.x * 2 + sub;
    const size_t base = tok * 3072;

    float* q_ = sq[sub]; float* k_ = sk[sub]; float* v_ = sv[sub]; float* w_ = sw[sub];

    for (int i = tid; i < 1024; i += 128) {
        const int h = i >> 7, d = i & 127;
        q_[h * 132 + d] = QKV[base + i];
        k_[h * 132 + d] = QKV[base + 1024 + i];
        v_[h * 132 + d] = QKV[base + 2048 + i];
    }
    __syncthreads();

    if (tid < 64) {
        const int h = tid >> 3, t = tid & 7;
        float s = 0.0f;
        #pragma unroll 8
        for (int d = 0; d < 128; d++)
            s += q_[h * 132 + d] * k_[t * 132 + d];
        w_[tid] = s * 0.08838834764831845f;      // 1/sqrt(128)
    }
    __syncthreads();

    if (tid < 8) {
        const int h = tid;
        float m = w_[h * 8];
        #pragma unroll
        for (int t = 1; t < 8; t++) m = fmaxf(m, w_[h * 8 + t]);
        float e[8], sum = 0.0f;
        #pragma unroll
        for (int t = 0; t < 8; t++) { e[t] = expf(w_[h * 8 + t] - m); sum += e[t]; }
        const float inv = 1.0f / sum;
        #pragma unroll
        for (int t = 0; t < 8; t++) w_[h * 8 + t] = e[t] * inv;
    }
    __syncthreads();

    const int d = tid;
    const size_t obase = tok * 1024;
    #pragma unroll
    for (int h = 0; h < 8; h++) {
        float o = 0.0f;
        #pragma unroll
        for (int t = 0; t < 8; t++)
            o += w_[h * 8 + t] * v_[t * 132 + d];
        Oh[obase + h * 128 + d] = __float2half_rn(o);
    }

    if (AW != nullptr && tid < 64)
        AW[tok * 64 + tid] = w_[tid];
}

// ============================================================================
extern "C" void kernel_launch(void* const* d_in, const int* in_sizes, int n_in,
                              void* d_out, int out_size)
{
    (void)in_sizes; (void)n_in;
    const float* x  = (const float*)d_in[0];
    const float* bq = (const float*)d_in[2];
    const float* bk = (const float*)d_in[4];
    const float* bv = (const float*)d_in[6];
    const float* b1 = (const float*)d_in[8];
    const float* b2 = (const float*)d_in[10];
    float* out = (float*)d_out;

    float *qkv, *bqkv;
    __half *xh, *aoh, *hh, *wthi, *wtlo;
    cudaGetSymbolAddress((void**)&qkv,  g_qkv);
    cudaGetSymbolAddress((void**)&bqkv, g_bqkv);
    cudaGetSymbolAddress((void**)&xh,   g_xh);
    cudaGetSymbolAddress((void**)&aoh,  g_aoh);
    cudaGetSymbolAddress((void**)&hh,   g_hh);
    cudaGetSymbolAddress((void**)&wthi, g_wthi);
    cudaGetSymbolAddress((void**)&wtlo, g_wtlo);

    cudaFuncSetAttribute(gemm_mma_f16x2,
                         cudaFuncAttributeMaxDynamicSharedMemorySize, SMEM_DYN);

    const int ff_elems   = M_TOK * DM;
    const int attn_elems = M_TOK * 64;
    float* aw = (out_size >= ff_elems + attn_elems) ? (out + ff_elems) : nullptr;

    // ---- prep: x -> fp16; all-5 weight transpose+split; concat qkv bias ---
    xconvert_kernel<<<(M_TOK * DM / 4 + 255) / 256, 256>>>(x, xh, M_TOK * DM / 4);
    wconvert_kernel<<<dim3(32, 32, 5), dim3(32, 8)>>>(
        (const float*)d_in[1], (const float*)d_in[3], (const float*)d_in[5],
        (const float*)d_in[7], (const float*)d_in[9], wthi, wtlo);
    cudaMemcpyAsync(bqkv,        bq, 1024 * sizeof(float), cudaMemcpyDeviceToDevice);
    cudaMemcpyAsync(bqkv + 1024, bk, 1024 * sizeof(float), cudaMemcpyDeviceToDevice);
    cudaMemcpyAsync(bqkv + 2048, bv, 1024 * sizeof(float), cudaMemcpyDeviceToDevice);

    dim3 block(256);

    // ---- fused QKV projection: N=3072, packed [tok][3072] fp32 ------------
    gemm_mma_f16x2<<<dim3(24, 128), block, SMEM_DYN>>>(xh,
        wthi, wtlo, bqkv, qkv, nullptr, 0, 3072);

    // ---- attention (emits fp16 for FFN1) ----------------------------------
    attn_kernel<<<M_TOK / 2, 256>>>(qkv, aoh, aw);

    // ---- FFN --------------------------------------------------------------
    gemm_mma_f16x2<<<dim3(8, 128), block, SMEM_DYN>>>(aoh,
        wthi + 3 * (size_t)DM * DM, wtlo + 3 * (size_t)DM * DM, b1,
        nullptr, hh, 1, 1024);
    gemm_mma_f16x2<<<dim3(8, 128), block, SMEM_DYN>>>(hh,
        wthi + 4 * (size_t)DM * DM, wtlo + 4 * (size_t)DM * DM, b2,
        out, nullptr, 0, 1024);
}

// round 15
// speedup vs baseline: 2.4809x; 1.8060x over previous
#include <cuda_runtime.h>
#include <cuda_fp16.h>
#include <cstdint>

// ============================================================================
// TransformerEncoderLayer (B=4,S=4096,D=1024, 8 local heads) on sm_103 base.
// R14: pure fp16 single-product GEMMs (A fp16 x W fp16, fp32 accum) — half
// the HMMA count of R10's fp16x2. QKV GEMM emits fp16 directly (halves attn
// DRAM reads). Skeleton: proven 128x128 CTA / 256 thr / BK=64 / SW128 /
// 3-stage cp.async issue-before-compute. Fused QKV (N=3072) + R8 attn.
// ============================================================================

static const int M_TOK = 16384;
static const int DM    = 1024;

// ---------------- scratch (__device__ globals; allocation-free rule) --------
__device__ __half g_qkvh[16384 * 3072];            // packed q|k|v per token, fp16
__device__ float  g_bqkv[3072];                    // concat bias
__device__ __half g_xh [16384 * 1024];             // x as fp16
__device__ __half g_aoh[16384 * 1024];             // attn out as fp16
__device__ __half g_hh [16384 * 1024];             // ffn1 out as fp16
__device__ __half g_wth[5][1024 * 1024];           // W^T fp16 [n][k] (q,k,v contiguous)

// ---------------- PTX helpers (sm_80-level; valid on sm_103 base) -----------
__device__ __forceinline__ uint32_t smem_u32(const void* p) {
    uint32_t a;
    asm("{ .reg .u64 t; cvta.to.shared.u64 t, %1; cvt.u32.u64 %0, t; }"
        : "=r"(a) : "l"(p));
    return a;
}
__device__ __forceinline__ void cpasync16(uint32_t saddr, const void* g) {
    asm volatile("cp.async.cg.shared.global [%0], [%1], 16;"
                 :: "r"(saddr), "l"(g));
}
#define CP_COMMIT() asm volatile("cp.async.commit_group;" ::: "memory")
#define CP_WAIT1()  asm volatile("cp.async.wait_group 1;" ::: "memory")

__device__ __forceinline__ void ldsm4(uint32_t r[4], uint32_t addr) {
    asm volatile("ldmatrix.sync.aligned.m8n8.x4.shared.b16 {%0,%1,%2,%3}, [%4];"
                 : "=r"(r[0]), "=r"(r[1]), "=r"(r[2]), "=r"(r[3]) : "r"(addr));
}
__device__ __forceinline__ void mma16816h(float c[4], const uint32_t a[4],
                                          uint32_t b0, uint32_t b1) {
    asm volatile(
        "mma.sync.aligned.m16n8k16.row.col.f32.f16.f16.f32 "
        "{%0,%1,%2,%3}, {%4,%5,%6,%7}, {%8,%9}, {%0,%1,%2,%3};"
        : "+f"(c[0]), "+f"(c[1]), "+f"(c[2]), "+f"(c[3])
        : "r"(a[0]), "r"(a[1]), "r"(a[2]), "r"(a[3]), "r"(b0), "r"(b1));
}

// smem: 3 stages x 32KB; stage = A@0(16K), W@16K(16K).
// Each operand: 128 rows x 128B (BK=64 fp16), SW128 swizzle.
static const int STAGE_BYTES = 32768;
static const int SMEM_DYN    = 3 * STAGE_BYTES;    // 96KB -> 2 CTAs/SM possible

// ============================================================================
// GEMM D[M x N] = A @ W + bias. A fp16 [m][1024], W^T fp16 [n][1024].
// CTA 128x128, 256 thr (8 warps: 2m x 4n, warp tile 64x32), BK=64, 3 stages.
// Out: fp32 Cf and/or fp16 Ch with leading dim Nld; optional ReLU.
// ============================================================================
__global__ __launch_bounds__(256, 2)
void gemm_mma_f16(const __half* __restrict__ A, const __half* __restrict__ B,
                  const float* __restrict__ bias,
                  float* __restrict__ Cf, __half* __restrict__ Ch,
                  int relu, int Nld)
{
    extern __shared__ char smem[];
    const uint32_t sbase = smem_u32(smem);
    const int tid  = threadIdx.x;
    const int lane = tid & 31;
    const int wid  = tid >> 5;
    const int wm   = wid >> 2;          // 0..1  (m: 64 each)
    const int wn   = wid & 3;           // 0..3  (n: 32 each)
    const int m0   = blockIdx.y * 128;
    const int n0   = blockIdx.x * 128;

    float acc[4][4][4];
    #pragma unroll
    for (int a = 0; a < 4; ++a)
        #pragma unroll
        for (int n = 0; n < 4; ++n)
            #pragma unroll
            for (int e = 0; e < 4; ++e) acc[a][n][e] = 0.0f;

    // ---- gmem->smem mapping: 8 threads per 128B row, all 8 granules -------
    const int lrow = tid >> 3;                  // 0..31, + j*32
    const int lc   = tid & 7;                   // 16B granule
    auto issue_tile = [&](int t) {
        const uint32_t st = sbase + (uint32_t)(t % 3) * (uint32_t)STAGE_BYTES;
        const int kt = t * 64;
        #pragma unroll
        for (int j = 0; j < 4; ++j) {
            const int row = j * 32 + lrow;
            const uint32_t so = (uint32_t)row * 128u +
                                (((uint32_t)lc * 16u) ^ (((uint32_t)row & 7u) << 4));
            const size_t ga = (size_t)(m0 + row) * 1024 + kt + lc * 8;
            const size_t gb = (size_t)(n0 + row) * 1024 + kt + lc * 8;
            cpasync16(st +          so, A + ga);
            cpasync16(st + 16384u + so, B + gb);
        }
    };

    // ---- ldmatrix per-thread constants -------------------------------------
    const int mi = lane >> 3, li = lane & 7;
    const uint32_t axor  = ((uint32_t)li) << 4;                 // swizzle xor
    const int      arow0 = wm * 64 + ((mi & 1) << 3) + li;      // + a*16
    const uint32_t acb0  = ((uint32_t)(mi >> 1)) << 4;          // + ks*32
    const int      brow0 = wn * 32 + ((mi >> 1) << 3) + li;     // + g*16
    const uint32_t bcb0  = ((uint32_t)(mi & 1)) << 4;           // + ks*32

    // ---- pipeline: 3-stage cp.async, issue-before-compute ------------------
    issue_tile(0); CP_COMMIT();
    issue_tile(1); CP_COMMIT();

    for (int t = 0; t < 16; ++t) {
        CP_WAIT1();
        __syncthreads();
        if (t + 2 < 16) issue_tile(t + 2);
        CP_COMMIT();

        const uint32_t st = sbase + (uint32_t)(t % 3) * (uint32_t)STAGE_BYTES;
        #pragma unroll
        for (int ks = 0; ks < 4; ++ks) {
            const uint32_t kc = (uint32_t)ks * 32u;
            uint32_t aF[4][4], bF[2][4];

            #pragma unroll
            for (int a = 0; a < 4; ++a)
                ldsm4(aF[a], st + (uint32_t)(arow0 + a * 16) * 128u + ((kc + acb0) ^ axor));
            #pragma unroll
            for (int g = 0; g < 2; ++g)
                ldsm4(bF[g], st + 16384u + (uint32_t)(brow0 + g * 16) * 128u + ((kc + bcb0) ^ axor));
            #pragma unroll
            for (int a = 0; a < 4; ++a)
                #pragma unroll
                for (int n = 0; n < 4; ++n)
                    mma16816h(acc[a][n], aF[a], bF[n >> 1][(n & 1) * 2], bF[n >> 1][(n & 1) * 2 + 1]);
        }
    }

    // ---- epilogue ----------------------------------------------------------
    const int er0 = m0 + wm * 64 + (lane >> 2);
    const int ec0 = n0 + wn * 32 + (lane & 3) * 2;
    #pragma unroll
    for (int a = 0; a < 4; ++a) {
        #pragma unroll
        for (int n = 0; n < 4; ++n) {
            const int r0 = er0 + a * 16, r1 = r0 + 8;
            const int c  = ec0 + n * 8;
            const float b0 = __ldg(bias + c), b1 = __ldg(bias + c + 1);
            float v00 = acc[a][n][0] + b0, v01 = acc[a][n][1] + b1;
            float v10 = acc[a][n][2] + b0, v11 = acc[a][n][3] + b1;
            if (relu) {
                v00 = fmaxf(v00, 0.0f); v01 = fmaxf(v01, 0.0f);
                v10 = fmaxf(v10, 0.0f); v11 = fmaxf(v11, 0.0f);
            }
            if (Cf) {
                *(float2*)(Cf + (size_t)r0 * Nld + c) = make_float2(v00, v01);
                *(float2*)(Cf + (size_t)r1 * Nld + c) = make_float2(v10, v11);
            }
            if (Ch) {
                *(__half2*)(Ch + (size_t)r0 * Nld + c) = __floats2half2_rn(v00, v01);
                *(__half2*)(Ch + (size_t)r1 * Nld + c) = __floats2half2_rn(v10, v11);
            }
        }
    }
}

// ============================================================================
// fp32 -> fp16 elementwise convert (for x)
// ============================================================================
__global__ void xconvert_kernel(const float* __restrict__ X,
                                __half* __restrict__ H, int n4)
{
    const int i = blockIdx.x * blockDim.x + threadIdx.x;
    if (i >= n4) return;
    const float4 v = ((const float4*)X)[i];
    ((__half2*)H)[i * 2 + 0] = __floats2half2_rn(v.x, v.y);
    ((__half2*)H)[i * 2 + 1] = __floats2half2_rn(v.z, v.w);
}

// ============================================================================
// All 5 weights: W [k][n] fp32 -> W^T fp16 [n][k]. gridDim.z selects W.
// ============================================================================
__global__ void wconvert_kernel(const float* __restrict__ W0, const float* __restrict__ W1,
                                const float* __restrict__ W2, const float* __restrict__ W3,
                                const float* __restrict__ W4,
                                __half* __restrict__ T)
{
    __shared__ float t[32][33];
    const int wi = blockIdx.z;
    const float* W = (wi == 0) ? W0 : (wi == 1) ? W1 : (wi == 2) ? W2
                   : (wi == 3) ? W3 : W4;
    __half* H = T + (size_t)wi * 1024 * 1024;

    const int k0 = blockIdx.y * 32, n0 = blockIdx.x * 32;
    const int tx = threadIdx.x, ty = threadIdx.y;  // 32 x 8
    #pragma unroll
    for (int i = 0; i < 4; ++i)
        t[ty + i*8][tx] = W[(size_t)(k0 + ty + i*8) * 1024 + n0 + tx];
    __syncthreads();
    #pragma unroll
    for (int i = 0; i < 4; ++i) {
        const float v = t[tx][ty + i*8];
        H[(size_t)(n0 + ty + i*8) * 1024 + k0 + tx] = __float2half_rn(v);
    }
}

// ============================================================================
// Per-token 8-head local attention; packed fp16 qkv [tok][3072] input;
// 2 tokens per 256-thread block; fp32 math in smem; emits fp16 ao + fp32 aw.
// ============================================================================
__global__ __launch_bounds__(256)
void attn_kernel(const __half* __restrict__ QKV,
                 __half* __restrict__ Oh, float* __restrict__ AW)
{
    __shared__ float sq[2][8 * 132];
    __shared__ float sk[2][8 * 132];
    __shared__ float sv[2][8 * 132];
    __shared__ float sw[2][64];

    const int sub = threadIdx.x >> 7;            // token within block
    const int tid = threadIdx.x & 127;
    const size_t tok  = (size_t)blockIdx.x * 2 + sub;
    const size_t base = tok * 3072;

    float* q_ = sq[sub]; float* k_ = sk[sub]; float* v_ = sv[sub]; float* w_ = sw[sub];

    // fp16 loads: 2 elems per iteration (half2), 512 half2 per operand
    const __half2* Q2 = (const __half2*)(QKV + base);
    const __half2* K2 = (const __half2*)(QKV + base + 1024);
    const __half2* V2 = (const __half2*)(QKV + base + 2048);
    for (int i = tid; i < 512; i += 128) {
        const int e = i * 2;                     // even elem index
        const int h = e >> 7, d = e & 127;       // d <= 126
        const float2 fq = __half22float2(Q2[i]);
        const float2 fk = __half22float2(K2[i]);
        const float2 fv = __half22float2(V2[i]);
        q_[h * 132 + d] = fq.x; q_[h * 132 + d + 1] = fq.y;
        k_[h * 132 + d] = fk.x; k_[h * 132 + d + 1] = fk.y;
        v_[h * 132 + d] = fv.x; v_[h * 132 + d + 1] = fv.y;
    }
    __syncthreads();

    if (tid < 64) {
        const int h = tid >> 3, t = tid & 7;
        float s = 0.0f;
        #pragma unroll 8
        for (int d = 0; d < 128; d++)
            s += q_[h * 132 + d] * k_[t * 132 + d];
        w_[tid] = s * 0.08838834764831845f;      // 1/sqrt(128)
    }
    __syncthreads();

    if (tid < 8) {
        const int h = tid;
        float m = w_[h * 8];
        #pragma unroll
        for (int t = 1; t < 8; t++) m = fmaxf(m, w_[h * 8 + t]);
        float e[8], sum = 0.0f;
        #pragma unroll
        for (int t = 0; t < 8; t++) { e[t] = expf(w_[h * 8 + t] - m); sum += e[t]; }
        const float inv = 1.0f / sum;
        #pragma unroll
        for (int t = 0; t < 8; t++) w_[h * 8 + t] = e[t] * inv;
    }
    __syncthreads();

    const int d = tid;
    const size_t obase = tok * 1024;
    #pragma unroll
    for (int h = 0; h < 8; h++) {
        float o = 0.0f;
        #pragma unroll
        for (int t = 0; t < 8; t++)
            o += w_[h * 8 + t] * v_[t * 132 + d];
        Oh[obase + h * 128 + d] = __float2half_rn(o);
    }

    if (AW != nullptr && tid < 64)
        AW[tok * 64 + tid] = w_[tid];
}

// ============================================================================
extern "C" void kernel_launch(void* const* d_in, const int* in_sizes, int n_in,
                              void* d_out, int out_size)
{
    (void)in_sizes; (void)n_in;
    const float* x  = (const float*)d_in[0];
    const float* bq = (const float*)d_in[2];
    const float* bk = (const float*)d_in[4];
    const float* bv = (const float*)d_in[6];
    const float* b1 = (const float*)d_in[8];
    const float* b2 = (const float*)d_in[10];
    float* out = (float*)d_out;

    float *bqkv;
    __half *qkvh, *xh, *aoh, *hh, *wth;
    cudaGetSymbolAddress((void**)&qkvh, g_qkvh);
    cudaGetSymbolAddress((void**)&bqkv, g_bqkv);
    cudaGetSymbolAddress((void**)&xh,   g_xh);
    cudaGetSymbolAddress((void**)&aoh,  g_aoh);
    cudaGetSymbolAddress((void**)&hh,   g_hh);
    cudaGetSymbolAddress((void**)&wth,  g_wth);

    cudaFuncSetAttribute(gemm_mma_f16,
                         cudaFuncAttributeMaxDynamicSharedMemorySize, SMEM_DYN);

    const int ff_elems   = M_TOK * DM;
    const int attn_elems = M_TOK * 64;
    float* aw = (out_size >= ff_elems + attn_elems) ? (out + ff_elems) : nullptr;

    // ---- prep: x -> fp16; all-5 weight transpose; concat qkv bias ---------
    xconvert_kernel<<<(M_TOK * DM / 4 + 255) / 256, 256>>>(x, xh, M_TOK * DM / 4);
    wconvert_kernel<<<dim3(32, 32, 5), dim3(32, 8)>>>(
        (const float*)d_in[1], (const float*)d_in[3], (const float*)d_in[5],
        (const float*)d_in[7], (const float*)d_in[9], wth);
    cudaMemcpyAsync(bqkv,        bq, 1024 * sizeof(float), cudaMemcpyDeviceToDevice);
    cudaMemcpyAsync(bqkv + 1024, bk, 1024 * sizeof(float), cudaMemcpyDeviceToDevice);
    cudaMemcpyAsync(bqkv + 2048, bv, 1024 * sizeof(float), cudaMemcpyDeviceToDevice);

    dim3 block(256);

    // ---- fused QKV projection: N=3072, packed [tok][3072] fp16 ------------
    gemm_mma_f16<<<dim3(24, 128), block, SMEM_DYN>>>(xh,
        wth, bqkv, nullptr, qkvh, 0, 3072);

    // ---- attention (emits fp16 for FFN1) ----------------------------------
    attn_kernel<<<M_TOK / 2, 256>>>(qkvh, aoh, aw);

    // ---- FFN --------------------------------------------------------------
    gemm_mma_f16<<<dim3(8, 128), block, SMEM_DYN>>>(aoh,
        wth + 3 * (size_t)DM * DM, b1, nullptr, hh, 1, 1024);
    gemm_mma_f16<<<dim3(8, 128), block, SMEM_DYN>>>(hh,
        wth + 4 * (size_t)DM * DM, b2, out, nullptr, 0, 1024);
}

// round 16
// speedup vs baseline: 2.5976x; 1.0470x over previous
#include <cuda_runtime.h>
#include <cuda_fp16.h>
#include <cstdint>

// ============================================================================
// TransformerEncoderLayer (B=4,S=4096,D=1024, 8 local heads) on sm_103 base.
// R15: R14 fp16 single-product GEMMs unchanged (proven 524us config).
// Attn reworked: half2 smem (half the crossbar bytes), v hoisted to regs in
// the out phase, 64 thr/token x 4 tokens/block (all lanes active).
// ============================================================================

static const int M_TOK = 16384;
static const int DM    = 1024;

// ---------------- scratch (__device__ globals; allocation-free rule) --------
__device__ __half g_qkvh[16384 * 3072];            // packed q|k|v per token, fp16
__device__ float  g_bqkv[3072];                    // concat bias
__device__ __half g_xh [16384 * 1024];             // x as fp16
__device__ __half g_aoh[16384 * 1024];             // attn out as fp16
__device__ __half g_hh [16384 * 1024];             // ffn1 out as fp16
__device__ __half g_wth[5][1024 * 1024];           // W^T fp16 [n][k] (q,k,v contiguous)

// ---------------- PTX helpers (sm_80-level; valid on sm_103 base) -----------
__device__ __forceinline__ uint32_t smem_u32(const void* p) {
    uint32_t a;
    asm("{ .reg .u64 t; cvta.to.shared.u64 t, %1; cvt.u32.u64 %0, t; }"
        : "=r"(a) : "l"(p));
    return a;
}
__device__ __forceinline__ void cpasync16(uint32_t saddr, const void* g) {
    asm volatile("cp.async.cg.shared.global [%0], [%1], 16;"
                 :: "r"(saddr), "l"(g));
}
#define CP_COMMIT() asm volatile("cp.async.commit_group;" ::: "memory")
#define CP_WAIT1()  asm volatile("cp.async.wait_group 1;" ::: "memory")

__device__ __forceinline__ void ldsm4(uint32_t r[4], uint32_t addr) {
    asm volatile("ldmatrix.sync.aligned.m8n8.x4.shared.b16 {%0,%1,%2,%3}, [%4];"
                 : "=r"(r[0]), "=r"(r[1]), "=r"(r[2]), "=r"(r[3]) : "r"(addr));
}
__device__ __forceinline__ void mma16816h(float c[4], const uint32_t a[4],
                                          uint32_t b0, uint32_t b1) {
    asm volatile(
        "mma.sync.aligned.m16n8k16.row.col.f32.f16.f16.f32 "
        "{%0,%1,%2,%3}, {%4,%5,%6,%7}, {%8,%9}, {%0,%1,%2,%3};"
        : "+f"(c[0]), "+f"(c[1]), "+f"(c[2]), "+f"(c[3])
        : "r"(a[0]), "r"(a[1]), "r"(a[2]), "r"(a[3]), "r"(b0), "r"(b1));
}

// smem: 3 stages x 32KB; stage = A@0(16K), W@16K(16K).
// Each operand: 128 rows x 128B (BK=64 fp16), SW128 swizzle.
static const int STAGE_BYTES = 32768;
static const int SMEM_DYN    = 3 * STAGE_BYTES;    // 96KB -> 2 CTAs/SM

// ============================================================================
// GEMM D[M x N] = A @ W + bias. A fp16 [m][1024], W^T fp16 [n][1024].
// CTA 128x128, 256 thr (8 warps: 2m x 4n, warp tile 64x32), BK=64, 3 stages.
// Out: fp32 Cf and/or fp16 Ch with leading dim Nld; optional ReLU.
// (UNCHANGED from R14 — proven 524us configuration.)
// ============================================================================
__global__ __launch_bounds__(256, 2)
void gemm_mma_f16(const __half* __restrict__ A, const __half* __restrict__ B,
                  const float* __restrict__ bias,
                  float* __restrict__ Cf, __half* __restrict__ Ch,
                  int relu, int Nld)
{
    extern __shared__ char smem[];
    const uint32_t sbase = smem_u32(smem);
    const int tid  = threadIdx.x;
    const int lane = tid & 31;
    const int wid  = tid >> 5;
    const int wm   = wid >> 2;          // 0..1  (m: 64 each)
    const int wn   = wid & 3;           // 0..3  (n: 32 each)
    const int m0   = blockIdx.y * 128;
    const int n0   = blockIdx.x * 128;

    float acc[4][4][4];
    #pragma unroll
    for (int a = 0; a < 4; ++a)
        #pragma unroll
        for (int n = 0; n < 4; ++n)
            #pragma unroll
            for (int e = 0; e < 4; ++e) acc[a][n][e] = 0.0f;

    const int lrow = tid >> 3;                  // 0..31, + j*32
    const int lc   = tid & 7;                   // 16B granule
    auto issue_tile = [&](int t) {
        const uint32_t st = sbase + (uint32_t)(t % 3) * (uint32_t)STAGE_BYTES;
        const int kt = t * 64;
        #pragma unroll
        for (int j = 0; j < 4; ++j) {
            const int row = j * 32 + lrow;
            const uint32_t so = (uint32_t)row * 128u +
                                (((uint32_t)lc * 16u) ^ (((uint32_t)row & 7u) << 4));
            const size_t ga = (size_t)(m0 + row) * 1024 + kt + lc * 8;
            const size_t gb = (size_t)(n0 + row) * 1024 + kt + lc * 8;
            cpasync16(st +          so, A + ga);
            cpasync16(st + 16384u + so, B + gb);
        }
    };

    const int mi = lane >> 3, li = lane & 7;
    const uint32_t axor  = ((uint32_t)li) << 4;
    const int      arow0 = wm * 64 + ((mi & 1) << 3) + li;
    const uint32_t acb0  = ((uint32_t)(mi >> 1)) << 4;
    const int      brow0 = wn * 32 + ((mi >> 1) << 3) + li;
    const uint32_t bcb0  = ((uint32_t)(mi & 1)) << 4;

    issue_tile(0); CP_COMMIT();
    issue_tile(1); CP_COMMIT();

    for (int t = 0; t < 16; ++t) {
        CP_WAIT1();
        __syncthreads();
        if (t + 2 < 16) issue_tile(t + 2);
        CP_COMMIT();

        const uint32_t st = sbase + (uint32_t)(t % 3) * (uint32_t)STAGE_BYTES;
        #pragma unroll
        for (int ks = 0; ks < 4; ++ks) {
            const uint32_t kc = (uint32_t)ks * 32u;
            uint32_t aF[4][4], bF[2][4];

            #pragma unroll
            for (int a = 0; a < 4; ++a)
                ldsm4(aF[a], st + (uint32_t)(arow0 + a * 16) * 128u + ((kc + acb0) ^ axor));
            #pragma unroll
            for (int g = 0; g < 2; ++g)
                ldsm4(bF[g], st + 16384u + (uint32_t)(brow0 + g * 16) * 128u + ((kc + bcb0) ^ axor));
            #pragma unroll
            for (int a = 0; a < 4; ++a)
                #pragma unroll
                for (int n = 0; n < 4; ++n)
                    mma16816h(acc[a][n], aF[a], bF[n >> 1][(n & 1) * 2], bF[n >> 1][(n & 1) * 2 + 1]);
        }
    }

    const int er0 = m0 + wm * 64 + (lane >> 2);
    const int ec0 = n0 + wn * 32 + (lane & 3) * 2;
    #pragma unroll
    for (int a = 0; a < 4; ++a) {
        #pragma unroll
        for (int n = 0; n < 4; ++n) {
            const int r0 = er0 + a * 16, r1 = r0 + 8;
            const int c  = ec0 + n * 8;
            const float b0 = __ldg(bias + c), b1 = __ldg(bias + c + 1);
            float v00 = acc[a][n][0] + b0, v01 = acc[a][n][1] + b1;
            float v10 = acc[a][n][2] + b0, v11 = acc[a][n][3] + b1;
            if (relu) {
                v00 = fmaxf(v00, 0.0f); v01 = fmaxf(v01, 0.0f);
                v10 = fmaxf(v10, 0.0f); v11 = fmaxf(v11, 0.0f);
            }
            if (Cf) {
                *(float2*)(Cf + (size_t)r0 * Nld + c) = make_float2(v00, v01);
                *(float2*)(Cf + (size_t)r1 * Nld + c) = make_float2(v10, v11);
            }
            if (Ch) {
                *(__half2*)(Ch + (size_t)r0 * Nld + c) = __floats2half2_rn(v00, v01);
                *(__half2*)(Ch + (size_t)r1 * Nld + c) = __floats2half2_rn(v10, v11);
            }
        }
    }
}

// ============================================================================
// fp32 -> fp16 elementwise convert (for x)
// ============================================================================
__global__ void xconvert_kernel(const float* __restrict__ X,
                                __half* __restrict__ H, int n4)
{
    const int i = blockIdx.x * blockDim.x + threadIdx.x;
    if (i >= n4) return;
    const float4 v = ((const float4*)X)[i];
    ((__half2*)H)[i * 2 + 0] = __floats2half2_rn(v.x, v.y);
    ((__half2*)H)[i * 2 + 1] = __floats2half2_rn(v.z, v.w);
}

// ============================================================================
// All 5 weights: W [k][n] fp32 -> W^T fp16 [n][k]. gridDim.z selects W.
// ============================================================================
__global__ void wconvert_kernel(const float* __restrict__ W0, const float* __restrict__ W1,
                                const float* __restrict__ W2, const float* __restrict__ W3,
                                const float* __restrict__ W4,
                                __half* __restrict__ T)
{
    __shared__ float t[32][33];
    const int wi = blockIdx.z;
    const float* W = (wi == 0) ? W0 : (wi == 1) ? W1 : (wi == 2) ? W2
                   : (wi == 3) ? W3 : W4;
    __half* H = T + (size_t)wi * 1024 * 1024;

    const int k0 = blockIdx.y * 32, n0 = blockIdx.x * 32;
    const int tx = threadIdx.x, ty = threadIdx.y;  // 32 x 8
    #pragma unroll
    for (int i = 0; i < 4; ++i)
        t[ty + i*8][tx] = W[(size_t)(k0 + ty + i*8) * 1024 + n0 + tx];
    __syncthreads();
    #pragma unroll
    for (int i = 0; i < 4; ++i) {
        const float v = t[tx][ty + i*8];
        H[(size_t)(n0 + ty + i*8) * 1024 + k0 + tx] = __float2half_rn(v);
    }
}

// ============================================================================
// Per-token 8-head local attention. Packed fp16 qkv [tok][3072].
// 4 tokens per 256-thread block, 64 threads per token.
// smem holds RAW half2 (halves crossbar bytes); fp32 math at use point
// (numerically identical to R14). v hoisted to regs in out phase.
// Layout: row stride 66 half2 per head (conflict-free in every phase).
// ============================================================================
__global__ __launch_bounds__(256)
void attn_kernel(const __half* __restrict__ QKV,
                 __half* __restrict__ Oh, float* __restrict__ AW)
{
    __shared__ uint32_t sq[4][8 * 66];   // half2 payload
    __shared__ uint32_t sk[4][8 * 66];
    __shared__ uint32_t sv[4][8 * 66];
    __shared__ float    sw[4][64];

    const int sub = threadIdx.x >> 6;            // token within block (0..3)
    const int tid = threadIdx.x & 63;            // 0..63
    const size_t tok = (size_t)blockIdx.x * 4 + sub;

    const uint32_t* Q2 = (const uint32_t*)(QKV + tok * 3072);
    const uint32_t* K2 = Q2 + 512;
    const uint32_t* V2 = Q2 + 1024;

    uint32_t* q_ = sq[sub]; uint32_t* k_ = sk[sub]; uint32_t* v_ = sv[sub];
    float* w_ = sw[sub];

    // load: 512 half2 per operand, 8 per thread, coalesced; raw copy (no cvt)
    #pragma unroll
    for (int it = 0; it < 8; ++it) {
        const int i = tid + it * 64;
        const int h = i >> 6, j = i & 63;        // head, d-pair
        q_[h * 66 + j] = Q2[i];
        k_[h * 66 + j] = K2[i];
        v_[h * 66 + j] = V2[i];
    }
    __syncthreads();

    // scores: all 64 threads, thread = (h,t); fp32 dot over 64 half2 pairs
    {
        const int h = tid >> 3, t = tid & 7;
        float s = 0.0f;
        #pragma unroll 8
        for (int j = 0; j < 64; ++j) {
            const float2 fq = __half22float2(*(const __half2*)&q_[h * 66 + j]);
            const float2 fk = __half22float2(*(const __half2*)&k_[t * 66 + j]);
            s += fq.x * fk.x + fq.y * fk.y;
        }
        w_[tid] = s * 0.08838834764831845f;      // 1/sqrt(128)
    }
    __syncthreads();

    // softmax over t (8 threads per token)
    if (tid < 8) {
        const int h = tid;
        float m = w_[h * 8];
        #pragma unroll
        for (int t = 1; t < 8; t++) m = fmaxf(m, w_[h * 8 + t]);
        float e[8], sum = 0.0f;
        #pragma unroll
        for (int t = 0; t < 8; t++) { e[t] = expf(w_[h * 8 + t] - m); sum += e[t]; }
        const float inv = 1.0f / sum;
        #pragma unroll
        for (int t = 0; t < 8; t++) w_[h * 8 + t] = e[t] * inv;
    }
    __syncthreads();

    // out: thread = d-pair j; hoist v[t][j] (8 half2) to regs, reuse over h
    {
        const int j = tid;
        float2 vf[8];
        #pragma unroll
        for (int t = 0; t < 8; ++t)
            vf[t] = __half22float2(*(const __half2*)&v_[t * 66 + j]);

        const size_t obase = tok * 1024;
        #pragma unroll
        for (int h = 0; h < 8; ++h) {
            float ox = 0.0f, oy = 0.0f;
            #pragma unroll
            for (int t = 0; t < 8; ++t) {
                const float w = w_[h * 8 + t];
                ox += w * vf[t].x;
                oy += w * vf[t].y;
            }
            *(__half2*)(Oh + obase + h * 128 + 2 * j) = __floats2half2_rn(ox, oy);
        }
    }

    if (AW != nullptr)
        AW[tok * 64 + tid] = w_[tid];
}

// ============================================================================
extern "C" void kernel_launch(void* const* d_in, const int* in_sizes, int n_in,
                              void* d_out, int out_size)
{
    (void)in_sizes; (void)n_in;
    const float* x  = (const float*)d_in[0];
    const float* bq = (const float*)d_in[2];
    const float* bk = (const float*)d_in[4];
    const float* bv = (const float*)d_in[6];
    const float* b1 = (const float*)d_in[8];
    const float* b2 = (const float*)d_in[10];
    float* out = (float*)d_out;

    float *bqkv;
    __half *qkvh, *xh, *aoh, *hh, *wth;
    cudaGetSymbolAddress((void**)&qkvh, g_qkvh);
    cudaGetSymbolAddress((void**)&bqkv, g_bqkv);
    cudaGetSymbolAddress((void**)&xh,   g_xh);
    cudaGetSymbolAddress((void**)&aoh,  g_aoh);
    cudaGetSymbolAddress((void**)&hh,   g_hh);
    cudaGetSymbolAddress((void**)&wth,  g_wth);

    cudaFuncSetAttribute(gemm_mma_f16,
                         cudaFuncAttributeMaxDynamicSharedMemorySize, SMEM_DYN);

    const int ff_elems   = M_TOK * DM;
    const int attn_elems = M_TOK * 64;
    float* aw = (out_size >= ff_elems + attn_elems) ? (out + ff_elems) : nullptr;

    // ---- prep: x -> fp16; all-5 weight transpose; concat qkv bias ---------
    xconvert_kernel<<<(M_TOK * DM / 4 + 255) / 256, 256>>>(x, xh, M_TOK * DM / 4);
    wconvert_kernel<<<dim3(32, 32, 5), dim3(32, 8)>>>(
        (const float*)d_in[1], (const float*)d_in[3], (const float*)d_in[5],
        (const float*)d_in[7], (const float*)d_in[9], wth);
    cudaMemcpyAsync(bqkv,        bq, 1024 * sizeof(float), cudaMemcpyDeviceToDevice);
    cudaMemcpyAsync(bqkv + 1024, bk, 1024 * sizeof(float), cudaMemcpyDeviceToDevice);
    cudaMemcpyAsync(bqkv + 2048, bv, 1024 * sizeof(float), cudaMemcpyDeviceToDevice);

    dim3 block(256);

    // ---- fused QKV projection: N=3072, packed [tok][3072] fp16 ------------
    gemm_mma_f16<<<dim3(24, 128), block, SMEM_DYN>>>(xh,
        wth, bqkv, nullptr, qkvh, 0, 3072);

    // ---- attention (emits fp16 for FFN1) ----------------------------------
    attn_kernel<<<M_TOK / 4, 256>>>(qkvh, aoh, aw);

    // ---- FFN --------------------------------------------------------------
    gemm_mma_f16<<<dim3(8, 128), block, SMEM_DYN>>>(aoh,
        wth + 3 * (size_t)DM * DM, b1, nullptr, hh, 1, 1024);
    gemm_mma_f16<<<dim3(8, 128), block, SMEM_DYN>>>(hh,
        wth + 4 * (size_t)DM * DM, b2, out, nullptr, 0, 1024);
}